// round 14
// baseline (speedup 1.0000x reference)
#include <cuda_runtime.h>
#include <cuda_fp16.h>
#include <cstdint>

typedef unsigned int u32;
typedef __half f16;

#define NN 8388608ULL      // 8192*1024
#define NW 1048576ULL      // 1024*1024

// ---------------- global scratch (single fp16 everywhere) ----------------
__device__ f16 g_Ah[3][NN];          // x fp16
__device__ f16 g_Qh[3][NN];          // q (pre-scaled by log2e/16)
__device__ f16 g_Kh[3][NN];          // k
__device__ f16 g_Vh[3][NN];          // v
__device__ f16 g_AOh[3][NN];         // attention out
__device__ f16 g_Wth[4][NW];         // W^T [q,k,v,o]

// ---------------- PTX helpers ----------------
__device__ __forceinline__ u32 smem_u32(const void* p) {
    u32 a;
    asm("{ .reg .u64 t; cvta.to.shared.u64 t, %1; cvt.u32.u64 %0, t; }" : "=r"(a) : "l"(p));
    return a;
}
__device__ __forceinline__ void cp16(u32 d, const void* s) {
    asm volatile("cp.async.cg.shared.global [%0], [%1], 16;" :: "r"(d), "l"(s));
}
__device__ __forceinline__ void cpcommit() { asm volatile("cp.async.commit_group;"); }
template<int N> __device__ __forceinline__ void cpwait() {
    asm volatile("cp.async.wait_group %0;" :: "n"(N));
}
__device__ __forceinline__ void ldm4(u32* r, u32 a) {
    asm volatile("ldmatrix.sync.aligned.m8n8.x4.shared.b16 {%0,%1,%2,%3}, [%4];"
                 : "=r"(r[0]), "=r"(r[1]), "=r"(r[2]), "=r"(r[3]) : "r"(a));
}
__device__ __forceinline__ void ldm4t(u32* r, u32 a) {
    asm volatile("ldmatrix.sync.aligned.m8n8.x4.trans.shared.b16 {%0,%1,%2,%3}, [%4];"
                 : "=r"(r[0]), "=r"(r[1]), "=r"(r[2]), "=r"(r[3]) : "r"(a));
}
__device__ __forceinline__ void mma_fp(float* c, const u32* a, u32 b0, u32 b1) {
    asm volatile(
        "mma.sync.aligned.m16n8k16.row.col.f32.f16.f16.f32 "
        "{%0,%1,%2,%3}, {%4,%5,%6,%7}, {%8,%9}, {%0,%1,%2,%3};"
        : "+f"(c[0]), "+f"(c[1]), "+f"(c[2]), "+f"(c[3])
        : "r"(a[0]), "r"(a[1]), "r"(a[2]), "r"(a[3]), "r"(b0), "r"(b1));
}
__device__ __forceinline__ u32 cvt_f16x2(float lo, float hi) {
    u32 r;
    asm("cvt.rn.f16x2.f32 %0, %1, %2;" : "=r"(r) : "f"(hi), "f"(lo));
    return r;
}
__device__ __forceinline__ void wstore2h(f16* H, size_t off, float v0, float v1) {
    u32 p = cvt_f16x2(v0, v1);
    *(u32*)(H + off) = p;
}
__device__ __forceinline__ void sts32(u32 a, u32 v) {
    asm volatile("st.shared.b32 [%0], %1;" :: "r"(a), "r"(v) : "memory");
}

#define QSCALE 0.09016844f   // (1/16) * log2(e)

// ============================================================
// GEMM core (fp16): 128x128 tile, BK=32, 256 thr, 8 warps (2m x 4n),
// warp 64x32. C = A @ B^T. Double-buffered cp.async.
// ============================================================
#define GMAT 10240
#define GBUF 20480
#define GEMM_SMEM 40960

__device__ __forceinline__ void stage_g(u32 sm,
    const f16* __restrict__ A, int lda,
    const f16* __restrict__ B, int ldb, int k0, int tid)
{
    const int r = tid >> 2, cc = tid & 3;
    const u32 so = r * 80 + cc * 16;
    const int co = k0 + cc * 8;
    cp16(sm + so,               A + (size_t)r * lda + co);
    cp16(sm + so + 5120,        A + (size_t)(r + 64) * lda + co);
    cp16(sm + GMAT + so,        B + (size_t)r * ldb + co);
    cp16(sm + GMAT + so + 5120, B + (size_t)(r + 64) * ldb + co);
}

__device__ __forceinline__ void gemm_core(u32 sm,
    const f16* __restrict__ A, int lda,
    const f16* __restrict__ B, int ldb, int nk, float c[4][4][4])
{
    const int tid = threadIdx.x, wid = tid >> 5, lane = tid & 31;
    const int wm = wid >> 2, wn = wid & 3;
    const int lr = lane & 15, lc = lane >> 4;

    stage_g(sm, A, lda, B, ldb, 0, tid);
    cpcommit();

#pragma unroll 1
    for (int kt = 0; kt < nk; kt++) {
        if (kt + 1 < nk) {
            stage_g(sm + ((kt + 1) & 1) * GBUF, A, lda, B, ldb, (kt + 1) * 32, tid);
            cpcommit();
            cpwait<1>();
        } else {
            cpwait<0>();
        }
        __syncthreads();
        const u32 base = sm + (kt & 1) * GBUF;
#pragma unroll
        for (int ks = 0; ks < 2; ks++) {
            u32 ah[4][4], bh[2][4];
            const u32 aoff = base + (wm * 64 + lr) * 80 + ks * 32 + lc * 16;
#pragma unroll
            for (int mf = 0; mf < 4; mf++)
                ldm4(ah[mf], aoff + mf * 1280);
            const u32 boff = base + GMAT + (wn * 32 + lr) * 80 + ks * 32 + lc * 16;
#pragma unroll
            for (int g = 0; g < 2; g++)
                ldm4(bh[g], boff + g * 1280);
#pragma unroll
            for (int mf = 0; mf < 4; mf++)
#pragma unroll
                for (int nf = 0; nf < 4; nf++) {
                    const int g = nf >> 1, od = nf & 1;
                    mma_fp(c[mf][nf], ah[mf], bh[g][od], bh[g][od + 2]);
                }
        }
        __syncthreads();
    }
}

// ============================================================
// hproj: batched QKV projections -> fp16 q/k/v (q pre-scaled)
// ============================================================
__global__ __launch_bounds__(256, 2) void hproj(
    const f16* __restrict__ AB,
    const float* __restrict__ bq, const float* __restrict__ bk,
    const float* __restrict__ bv)
{
    extern __shared__ __align__(16) char smraw[];
    const u32 sm = smem_u32(smraw);
    const int s = blockIdx.z;
    const int bm = blockIdx.y << 7;
    const int bnG = blockIdx.x << 7;
    const int p = bnG >> 10, bnL = bnG & 1023;

    const float* bias = (p == 0) ? bq : (p == 1) ? bk : bv;
    f16* oh = (p == 0) ? g_Qh[s] : (p == 1) ? g_Kh[s] : g_Vh[s];
    const float osc = (p == 0) ? QSCALE : 1.0f;

    float c[4][4][4];
#pragma unroll
    for (int i = 0; i < 4; i++)
#pragma unroll
        for (int j = 0; j < 4; j++)
#pragma unroll
            for (int k = 0; k < 4; k++) c[i][j][k] = 0.f;

    gemm_core(sm, AB + s * NN + (size_t)bm * 1024, 1024,
              &g_Wth[0][0] + (size_t)bnG * 1024, 1024, 32, c);

    const int wid = threadIdx.x >> 5, lane = threadIdx.x & 31;
    const int wm = wid >> 2, wn = wid & 3;
    const int rbase = bm + wm * 64 + (lane >> 2);
    const int cbase = bnL + wn * 32 + 2 * (lane & 3);
#pragma unroll
    for (int mf = 0; mf < 4; mf++)
#pragma unroll
        for (int nf = 0; nf < 4; nf++) {
            const int col = cbase + nf * 8;
            const float b0 = bias[col], b1 = bias[col + 1];
            const int row = rbase + mf * 16;
            wstore2h(oh, (size_t)row * 1024 + col,
                     (c[mf][nf][0] + b0) * osc, (c[mf][nf][1] + b1) * osc);
            wstore2h(oh, (size_t)(row + 8) * 1024 + col,
                     (c[mf][nf][2] + b0) * osc, (c[mf][nf][3] + b1) * osc);
        }
}

// ============================================================
// hout: batched output projection -> fp32 (B,L,3,D)
// ============================================================
__global__ __launch_bounds__(256, 2) void hout(
    const f16* __restrict__ AOB,
    const float* __restrict__ bo, float* __restrict__ out)
{
    extern __shared__ __align__(16) char smraw[];
    const u32 sm = smem_u32(smraw);
    const int s = blockIdx.z;
    const int bm = blockIdx.y << 7, bn = blockIdx.x << 7;

    float c[4][4][4];
#pragma unroll
    for (int i = 0; i < 4; i++)
#pragma unroll
        for (int j = 0; j < 4; j++)
#pragma unroll
            for (int k = 0; k < 4; k++) c[i][j][k] = 0.f;

    gemm_core(sm, AOB + s * NN + (size_t)bm * 1024, 1024,
              &g_Wth[3][0] + (size_t)bn * 1024, 1024, 32, c);

    float* outF = out + s * 1024;
    const int wid = threadIdx.x >> 5, lane = threadIdx.x & 31;
    const int wm = wid >> 2, wn = wid & 3;
    const int rbase = bm + wm * 64 + (lane >> 2);
    const int cbase = bn + wn * 32 + 2 * (lane & 3);
#pragma unroll
    for (int mf = 0; mf < 4; mf++)
#pragma unroll
        for (int nf = 0; nf < 4; nf++) {
            const int col = cbase + nf * 8;
            const float b0 = bo[col], b1 = bo[col + 1];
            const int row = rbase + mf * 16;
            *(float2*)(outF + (size_t)row * 3072 + col) =
                make_float2(c[mf][nf][0] + b0, c[mf][nf][1] + b1);
            *(float2*)(outF + (size_t)(row + 8) * 3072 + col) =
                make_float2(c[mf][nf][2] + b0, c[mf][nf][3] + b1);
        }
}

// ============================================================
// hattn: fused dual attention, 512 threads (16 warps), warp tile 16x16.
// Scores use pre-scaled q -> p = exp2f(sa+sb). Per-thread regs ~100.
// smem: Q3+K3+V3+P3 tiles = ~109KB + rowsums. 1 CTA/SM, 16 warps.
// ============================================================
#define AROW 144
#define ATILE 9216
#define AQ 0
#define AK 27648
#define AV 55296
#define AP 82944
#define ASL 110592
#define ATTN_SMEM 111360

__device__ __forceinline__ void stage64(u32 dst, const void* __restrict__ src16) {
    const char* src = (const char*)src16;
    const int t = threadIdx.x;
    const int r = t >> 3, cc = t & 7;      // 512 threads = 64 rows x 8 chunks
    cp16(dst + r * AROW + cc * 16, src + (size_t)r * 2048 + cc * 16);
}

__global__ __launch_bounds__(512, 1) void hattn()
{
    extern __shared__ __align__(16) char smraw[];
    const u32 sm = smem_u32(smraw);
    float* sL = (float*)(smraw + ASL);

    const int tid = threadIdx.x, wid = tid >> 5, lane = tid & 31;
    const int bh = blockIdx.y, b = bh >> 4, h = bh & 15;
    const int i0 = blockIdx.x << 6;

    const int wm = wid & 3, wn = wid >> 2;    // 4 row-groups x 4 col-groups
    const int lr = lane & 15, lc = lane >> 4;

    if (tid < 192) sL[tid] = 0.f;

    const size_t qoff = ((size_t)((b << 10) + i0)) * 1024 + (h << 6);
    const size_t koff = ((size_t)(b << 10)) * 1024 + (h << 6);
    const void* Qp[3] = { g_Qh[0] + qoff, g_Qh[1] + qoff, g_Qh[2] + qoff };
    const void* Kp[3] = { g_Kh[0] + koff, g_Kh[1] + koff, g_Kh[2] + koff };
    const void* Vp[3] = { g_Vh[0] + koff, g_Vh[1] + koff, g_Vh[2] + koff };

    // prologue: group0 = {Q, K(0)}, group1 = {V(0)}
#pragma unroll
    for (int m = 0; m < 3; m++) stage64(sm + AQ + m * ATILE, Qp[m]);
#pragma unroll
    for (int m = 0; m < 3; m++) stage64(sm + AK + m * ATILE, Kp[m]);
    cpcommit();
#pragma unroll
    for (int m = 0; m < 3; m++) stage64(sm + AV + m * ATILE, Vp[m]);
    cpcommit();

    float co[3][2][4];      // [o][nf(d8)][frag]
    float Lsum[3][2];
#pragma unroll
    for (int o = 0; o < 3; o++) {
        Lsum[o][0] = 0.f; Lsum[o][1] = 0.f;
#pragma unroll
        for (int nf = 0; nf < 2; nf++)
#pragma unroll
            for (int k = 0; k < 4; k++) co[o][nf][k] = 0.f;
    }

#pragma unroll 1
    for (int kt = 0; kt < 16; kt++) {
        cpwait<1>();                 // Q + K(kt) ready
        __syncthreads();

        // ---- score MMAs: warp computes rows wm*16..+16, keys wn*16..+16 ----
        float sc[3][2][4];
#pragma unroll
        for (int s3 = 0; s3 < 3; s3++)
#pragma unroll
            for (int nf = 0; nf < 2; nf++)
#pragma unroll
                for (int k = 0; k < 4; k++) sc[s3][nf][k] = 0.f;

#pragma unroll
        for (int s3 = 0; s3 < 3; s3++) {
            const u32 qb = sm + AQ + s3 * ATILE + (wm * 16 + lr) * AROW + lc * 16;
            const u32 kb = sm + AK + s3 * ATILE + (wn * 16 + lr) * AROW + lc * 16;
#pragma unroll
            for (int ks = 0; ks < 4; ks++) {
                u32 qh[4], kh[4];
                ldm4(qh, qb + ks * 32);
                ldm4(kh, kb + ks * 32);
#pragma unroll
                for (int nf = 0; nf < 2; nf++)
                    mma_fp(sc[s3][nf], qh, kh[nf], kh[nf + 2]);
            }
        }
        __syncthreads();             // done reading K(kt)
        if (kt + 1 < 16) {
#pragma unroll
            for (int m = 0; m < 3; m++)
                stage64(sm + AK + m * ATILE, (const char*)Kp[m] + (size_t)(kt + 1) * 131072);
        }
        cpcommit();                  // group {K(kt+1)}

        // ---- p = exp2(sa + sb) -> fp16, to P smem (q pre-scaled) ----
#pragma unroll
        for (int o = 0; o < 3; o++) {
            const int sa = (o == 0) ? 1 : 0;
            const int sb = (o == 2) ? 1 : 2;
#pragma unroll
            for (int nf = 0; nf < 2; nf++) {
                const float p0 = exp2f(sc[sa][nf][0] + sc[sb][nf][0]);
                const float p1 = exp2f(sc[sa][nf][1] + sc[sb][nf][1]);
                const float p2 = exp2f(sc[sa][nf][2] + sc[sb][nf][2]);
                const float p3 = exp2f(sc[sa][nf][3] + sc[sb][nf][3]);
                Lsum[o][0] += p0 + p1;
                Lsum[o][1] += p2 + p3;
                const int row = wm * 16 + (lane >> 2);
                const int col = wn * 16 + nf * 8 + 2 * (lane & 3);
                const u32 ad = sm + AP + o * ATILE + row * AROW + col * 2;
                sts32(ad,            cvt_f16x2(p0, p1));
                sts32(ad + 8 * AROW, cvt_f16x2(p2, p3));
            }
        }

        cpwait<1>();                 // V(kt) ready
        __syncthreads();             // P visible

        // ---- PV MMAs: warp computes rows wm*16..+16, d cols wn*16..+16 ----
#pragma unroll
        for (int o = 0; o < 3; o++) {
            const u32 pb = sm + AP + o * ATILE + (wm * 16 + lr) * AROW + lc * 16;
            const u32 vb = sm + AV + o * ATILE + lr * AROW + wn * 32 + lc * 16;
#pragma unroll
            for (int ks = 0; ks < 4; ks++) {
                u32 ph[4], vh[4];
                ldm4(ph, pb + ks * 32);
                ldm4t(vh, vb + ks * 16 * AROW);
#pragma unroll
                for (int nf = 0; nf < 2; nf++)
                    mma_fp(co[o][nf], ph, vh[2 * nf], vh[2 * nf + 1]);
            }
        }
        __syncthreads();             // done reading V(kt) and P
        if (kt + 1 < 16) {
#pragma unroll
            for (int m = 0; m < 3; m++)
                stage64(sm + AV + m * ATILE, (const char*)Vp[m] + (size_t)(kt + 1) * 131072);
        }
        cpcommit();                  // group {V(kt+1)}
    }

    // ---- row-sum reduction into sL (4 key-group warps add per row) ----
#pragma unroll
    for (int o = 0; o < 3; o++)
#pragma unroll
        for (int sl = 0; sl < 2; sl++) {
            float v = Lsum[o][sl];
            v += __shfl_xor_sync(0xffffffffu, v, 1);
            v += __shfl_xor_sync(0xffffffffu, v, 2);
            if ((lane & 3) == 0) {
                const int row = wm * 16 + (lane >> 2) + sl * 8;
                atomicAdd(&sL[o * 64 + row], v);
            }
        }
    __syncthreads();

    // ---- epilogue: normalize + write AO (fp16) ----
#pragma unroll
    for (int o = 0; o < 3; o++) {
        f16* AH = g_AOh[o];
        const int rl0 = wm * 16 + (lane >> 2);
        const int rl1 = rl0 + 8;
        const float iv0 = 1.0f / sL[o * 64 + rl0];
        const float iv1 = 1.0f / sL[o * 64 + rl1];
#pragma unroll
        for (int nf = 0; nf < 2; nf++) {
            const int cl = wn * 16 + nf * 8 + 2 * (lane & 3);
            const size_t ga = ((size_t)((b << 10) + i0 + rl0)) * 1024 + (h << 6) + cl;
            const size_t gb2 = ((size_t)((b << 10) + i0 + rl1)) * 1024 + (h << 6) + cl;
            wstore2h(AH, ga,  co[o][nf][0] * iv0, co[o][nf][1] * iv0);
            wstore2h(AH, gb2, co[o][nf][2] * iv1, co[o][nf][3] * iv1);
        }
    }
}

// ============================================================
// split_all: x -> fp16, all 3 streams, one launch
// ============================================================
__global__ __launch_bounds__(256) void split_all(const float* __restrict__ x)
{
    const size_t gid = (size_t)blockIdx.x * 256 + threadIdx.x;
    const int s = (int)(gid >> 21);
    const size_t t = gid & 2097151ULL;
    const size_t idx = t * 4;
    const int m = (int)(idx >> 10), col = (int)(idx & 1023);
    const float4 v = *(const float4*)(x + ((size_t)m * 3 + s) * 1024 + col);
    f16* hi = &g_Ah[0][0] + s * NN + idx;
    ((u32*)hi)[0] = cvt_f16x2(v.x, v.y);
    ((u32*)hi)[1] = cvt_f16x2(v.z, v.w);
}

// ============================================================
// transposeAll: W^T (fp16) for all 4 weights
// ============================================================
__global__ __launch_bounds__(256) void transposeAll(
    const float* __restrict__ W0, const float* __restrict__ W1,
    const float* __restrict__ W2, const float* __restrict__ W3)
{
    __shared__ float t[32][33];
    const int w = blockIdx.z;
    const float* W = (w == 0) ? W0 : (w == 1) ? W1 : (w == 2) ? W2 : W3;
    f16* Th = &g_Wth[0][0] + (size_t)w * NW;
    int n0 = blockIdx.x << 5, k0 = blockIdx.y << 5;
    int tx = threadIdx.x, ty = threadIdx.y;
    for (int r = ty; r < 32; r += 8)
        t[r][tx] = W[(size_t)(k0 + r) * 1024 + n0 + tx];
    __syncthreads();
    for (int r = ty; r < 32; r += 8)
        Th[(size_t)(n0 + r) * 1024 + k0 + tx] = __float2half_rn(t[tx][r]);
}

// ============================================================
// Launch
// ============================================================
extern "C" void kernel_launch(void* const* d_in, const int* in_sizes, int n_in,
                              void* d_out, int out_size)
{
    const float* x  = (const float*)d_in[0];
    const float* Wq = (const float*)d_in[1];
    const float* bq = (const float*)d_in[2];
    const float* Wk = (const float*)d_in[3];
    const float* bk = (const float*)d_in[4];
    const float* Wv = (const float*)d_in[5];
    const float* bv = (const float*)d_in[6];
    const float* Wo = (const float*)d_in[7];
    const float* bo = (const float*)d_in[8];
    float* out = (float*)d_out;

    static bool attr_set = false;
    if (!attr_set) {
        cudaFuncSetAttribute(hproj, cudaFuncAttributeMaxDynamicSharedMemorySize, GEMM_SMEM);
        cudaFuncSetAttribute(hout, cudaFuncAttributeMaxDynamicSharedMemorySize, GEMM_SMEM);
        cudaFuncSetAttribute(hattn, cudaFuncAttributeMaxDynamicSharedMemorySize, ATTN_SMEM);
        attr_set = true;
    }

    f16 *Ah, *AOh;
    cudaGetSymbolAddress((void**)&Ah, g_Ah);
    cudaGetSymbolAddress((void**)&AOh, g_AOh);

    split_all<<<24576, 256>>>(x);
    transposeAll<<<dim3(32, 32, 4), dim3(32, 8)>>>(Wq, Wk, Wv, Wo);
    hproj<<<dim3(24, 64, 3), 256, GEMM_SMEM>>>(Ah, bq, bk, bv);
    hattn<<<dim3(16, 128), 512, ATTN_SMEM>>>();
    hout<<<dim3(8, 64, 3), 256, GEMM_SMEM>>>(AOh, bo, out);
}

// round 17
// speedup vs baseline: 1.1949x; 1.1949x over previous
#include <cuda_runtime.h>
#include <cuda_fp16.h>
#include <cstdint>

typedef unsigned int u32;
typedef __half f16;

#define NN 8388608ULL      // 8192*1024
#define NW 1048576ULL      // 1024*1024

// ---------------- global scratch (single fp16 everywhere) ----------------
__device__ f16 g_Ah[3][NN];          // x fp16
__device__ f16 g_Qh[3][NN];          // q (pre-scaled by log2e/16)
__device__ f16 g_Kh[3][NN];          // k
__device__ f16 g_Vh[3][NN];          // v
__device__ f16 g_AOh[3][NN];         // attention out
__device__ f16 g_Wth[4][NW];         // W^T [q,k,v,o]

// ---------------- PTX helpers ----------------
__device__ __forceinline__ u32 smem_u32(const void* p) {
    u32 a;
    asm("{ .reg .u64 t; cvta.to.shared.u64 t, %1; cvt.u32.u64 %0, t; }" : "=r"(a) : "l"(p));
    return a;
}
__device__ __forceinline__ void cp16(u32 d, const void* s) {
    asm volatile("cp.async.cg.shared.global [%0], [%1], 16;" :: "r"(d), "l"(s));
}
__device__ __forceinline__ void cpcommit() { asm volatile("cp.async.commit_group;"); }
template<int N> __device__ __forceinline__ void cpwait() {
    asm volatile("cp.async.wait_group %0;" :: "n"(N));
}
__device__ __forceinline__ void ldm4(u32* r, u32 a) {
    asm volatile("ldmatrix.sync.aligned.m8n8.x4.shared.b16 {%0,%1,%2,%3}, [%4];"
                 : "=r"(r[0]), "=r"(r[1]), "=r"(r[2]), "=r"(r[3]) : "r"(a));
}
__device__ __forceinline__ void ldm4t(u32* r, u32 a) {
    asm volatile("ldmatrix.sync.aligned.m8n8.x4.trans.shared.b16 {%0,%1,%2,%3}, [%4];"
                 : "=r"(r[0]), "=r"(r[1]), "=r"(r[2]), "=r"(r[3]) : "r"(a));
}
__device__ __forceinline__ void mma_fp(float* c, const u32* a, u32 b0, u32 b1) {
    asm volatile(
        "mma.sync.aligned.m16n8k16.row.col.f32.f16.f16.f32 "
        "{%0,%1,%2,%3}, {%4,%5,%6,%7}, {%8,%9}, {%0,%1,%2,%3};"
        : "+f"(c[0]), "+f"(c[1]), "+f"(c[2]), "+f"(c[3])
        : "r"(a[0]), "r"(a[1]), "r"(a[2]), "r"(a[3]), "r"(b0), "r"(b1));
}
__device__ __forceinline__ u32 cvt_f16x2(float lo, float hi) {
    u32 r;
    asm("cvt.rn.f16x2.f32 %0, %1, %2;" : "=r"(r) : "f"(hi), "f"(lo));
    return r;
}
__device__ __forceinline__ float ex2(float x) {
    float r;
    asm("ex2.approx.f32 %0, %1;" : "=f"(r) : "f"(x));
    return r;
}
__device__ __forceinline__ void wstore2h(f16* H, size_t off, float v0, float v1) {
    u32 p = cvt_f16x2(v0, v1);
    *(u32*)(H + off) = p;
}

#define QSCALE 0.09016844f   // (1/16) * log2(e)
#define ONESH2 0x3C003C00u

// ============================================================
// GEMM core (fp16): 128x128 tile, BK=32, 256 thr, 8 warps (2m x 4n),
// warp 64x32. C = A @ B^T. Double-buffered cp.async.
// ============================================================
#define GMAT 10240
#define GBUF 20480
#define GEMM_SMEM 40960

__device__ __forceinline__ void stage_g(u32 sm,
    const f16* __restrict__ A, int lda,
    const f16* __restrict__ B, int ldb, int k0, int tid)
{
    const int r = tid >> 2, cc = tid & 3;
    const u32 so = r * 80 + cc * 16;
    const int co = k0 + cc * 8;
    cp16(sm + so,               A + (size_t)r * lda + co);
    cp16(sm + so + 5120,        A + (size_t)(r + 64) * lda + co);
    cp16(sm + GMAT + so,        B + (size_t)r * ldb + co);
    cp16(sm + GMAT + so + 5120, B + (size_t)(r + 64) * ldb + co);
}

__device__ __forceinline__ void gemm_core(u32 sm,
    const f16* __restrict__ A, int lda,
    const f16* __restrict__ B, int ldb, int nk, float c[4][4][4])
{
    const int tid = threadIdx.x, wid = tid >> 5, lane = tid & 31;
    const int wm = wid >> 2, wn = wid & 3;
    const int lr = lane & 15, lc = lane >> 4;

    stage_g(sm, A, lda, B, ldb, 0, tid);
    cpcommit();

#pragma unroll 1
    for (int kt = 0; kt < nk; kt++) {
        if (kt + 1 < nk) {
            stage_g(sm + ((kt + 1) & 1) * GBUF, A, lda, B, ldb, (kt + 1) * 32, tid);
            cpcommit();
            cpwait<1>();
        } else {
            cpwait<0>();
        }
        __syncthreads();
        const u32 base = sm + (kt & 1) * GBUF;
#pragma unroll
        for (int ks = 0; ks < 2; ks++) {
            u32 ah[4][4], bh[2][4];
            const u32 aoff = base + (wm * 64 + lr) * 80 + ks * 32 + lc * 16;
#pragma unroll
            for (int mf = 0; mf < 4; mf++)
                ldm4(ah[mf], aoff + mf * 1280);
            const u32 boff = base + GMAT + (wn * 32 + lr) * 80 + ks * 32 + lc * 16;
#pragma unroll
            for (int g = 0; g < 2; g++)
                ldm4(bh[g], boff + g * 1280);
#pragma unroll
            for (int mf = 0; mf < 4; mf++)
#pragma unroll
                for (int nf = 0; nf < 4; nf++) {
                    const int g = nf >> 1, od = nf & 1;
                    mma_fp(c[mf][nf], ah[mf], bh[g][od], bh[g][od + 2]);
                }
        }
        __syncthreads();
    }
}

// ============================================================
// hproj: batched QKV projections -> fp16 q/k/v (q pre-scaled)
// ============================================================
__global__ __launch_bounds__(256, 2) void hproj(
    const f16* __restrict__ AB,
    const float* __restrict__ bq, const float* __restrict__ bk,
    const float* __restrict__ bv)
{
    extern __shared__ __align__(16) char smraw[];
    const u32 sm = smem_u32(smraw);
    const int s = blockIdx.z;
    const int bm = blockIdx.y << 7;
    const int bnG = blockIdx.x << 7;
    const int p = bnG >> 10, bnL = bnG & 1023;

    const float* bias = (p == 0) ? bq : (p == 1) ? bk : bv;
    f16* oh = (p == 0) ? g_Qh[s] : (p == 1) ? g_Kh[s] : g_Vh[s];
    const float osc = (p == 0) ? QSCALE : 1.0f;

    float c[4][4][4];
#pragma unroll
    for (int i = 0; i < 4; i++)
#pragma unroll
        for (int j = 0; j < 4; j++)
#pragma unroll
            for (int k = 0; k < 4; k++) c[i][j][k] = 0.f;

    gemm_core(sm, AB + s * NN + (size_t)bm * 1024, 1024,
              &g_Wth[0][0] + (size_t)bnG * 1024, 1024, 32, c);

    const int wid = threadIdx.x >> 5, lane = threadIdx.x & 31;
    const int wm = wid >> 2, wn = wid & 3;
    const int rbase = bm + wm * 64 + (lane >> 2);
    const int cbase = bnL + wn * 32 + 2 * (lane & 3);
#pragma unroll
    for (int mf = 0; mf < 4; mf++)
#pragma unroll
        for (int nf = 0; nf < 4; nf++) {
            const int col = cbase + nf * 8;
            const float b0 = bias[col], b1 = bias[col + 1];
            const int row = rbase + mf * 16;
            wstore2h(oh, (size_t)row * 1024 + col,
                     (c[mf][nf][0] + b0) * osc, (c[mf][nf][1] + b1) * osc);
            wstore2h(oh, (size_t)(row + 8) * 1024 + col,
                     (c[mf][nf][2] + b0) * osc, (c[mf][nf][3] + b1) * osc);
        }
}

// ============================================================
// hout: batched output projection -> fp32 (B,L,3,D)
// ============================================================
__global__ __launch_bounds__(256, 2) void hout(
    const f16* __restrict__ AOB,
    const float* __restrict__ bo, float* __restrict__ out)
{
    extern __shared__ __align__(16) char smraw[];
    const u32 sm = smem_u32(smraw);
    const int s = blockIdx.z;
    const int bm = blockIdx.y << 7, bn = blockIdx.x << 7;

    float c[4][4][4];
#pragma unroll
    for (int i = 0; i < 4; i++)
#pragma unroll
        for (int j = 0; j < 4; j++)
#pragma unroll
            for (int k = 0; k < 4; k++) c[i][j][k] = 0.f;

    gemm_core(sm, AOB + s * NN + (size_t)bm * 1024, 1024,
              &g_Wth[3][0] + (size_t)bn * 1024, 1024, 32, c);

    float* outF = out + s * 1024;
    const int wid = threadIdx.x >> 5, lane = threadIdx.x & 31;
    const int wm = wid >> 2, wn = wid & 3;
    const int rbase = bm + wm * 64 + (lane >> 2);
    const int cbase = bn + wn * 32 + 2 * (lane & 3);
#pragma unroll
    for (int mf = 0; mf < 4; mf++)
#pragma unroll
        for (int nf = 0; nf < 4; nf++) {
            const int col = cbase + nf * 8;
            const float b0 = bo[col], b1 = bo[col + 1];
            const int row = rbase + mf * 16;
            *(float2*)(outF + (size_t)row * 3072 + col) =
                make_float2(c[mf][nf][0] + b0, c[mf][nf][1] + b1);
            *(float2*)(outF + (size_t)(row + 8) * 3072 + col) =
                make_float2(c[mf][nf][2] + b0, c[mf][nf][3] + b1);
        }
}

// ============================================================
// hattn v3 (fixed): register-P fusion, CTA = 128 q-rows x one bh,
// 256 thr, 8 warps; warp = 16 q-rows x all 64 keys of a tile.
// Q region now FULL 128 rows x 64 d per stream (3 x 18432B).
// K/V: 64-row tiles, double-buffered. P stays in registers; row sums
// via ones-vector MMA. 2 barriers per k-tile.
// ============================================================
#define AROW 144
#define AQT  18432         // Q tile: 128 rows x 144B
#define ATILE 9216         // K/V tile: 64 rows x 144B
#define AQ    0            // 3 x 18432 = 55296
#define AKB0  55296
#define AKB1  82944
#define AVB0  110592
#define AVB1  138240
#define ATTN_SMEM 165888

__device__ __forceinline__ void stage64(u32 dst, const f16* __restrict__ src) {
    const int t = threadIdx.x;
    const int r0 = t >> 3, cc = t & 7, r1 = r0 + 32;
    cp16(dst + r0 * AROW + cc * 16, src + (size_t)r0 * 1024 + cc * 8);
    cp16(dst + r1 * AROW + cc * 16, src + (size_t)r1 * 1024 + cc * 8);
}
__device__ __forceinline__ void stage128(u32 dst, const f16* __restrict__ src) {
    const int t = threadIdx.x;
#pragma unroll
    for (int it = 0; it < 4; it++) {
        const int idx = it * 256 + t;
        const int r = idx >> 3, cc = idx & 7;
        cp16(dst + r * AROW + cc * 16, src + (size_t)r * 1024 + cc * 8);
    }
}

__global__ __launch_bounds__(256, 1) void hattn()
{
    extern __shared__ __align__(16) char smraw[];
    const u32 sm = smem_u32(smraw);

    const int tid = threadIdx.x, wid = tid >> 5, lane = tid & 31;
    const int bh = blockIdx.y, b = bh >> 4, h = bh & 15;
    const int i0 = blockIdx.x << 7;
    const int lr = lane & 15, lc = lane >> 4;

    const size_t qoff = ((size_t)((b << 10) + i0)) * 1024 + (h << 6);
    const size_t koff = ((size_t)(b << 10)) * 1024 + (h << 6);
    const f16* Qp[3] = { g_Qh[0] + qoff, g_Qh[1] + qoff, g_Qh[2] + qoff };
    const f16* Kp[3] = { g_Kh[0] + koff, g_Kh[1] + koff, g_Kh[2] + koff };
    const f16* Vp[3] = { g_Vh[0] + koff, g_Vh[1] + koff, g_Vh[2] + koff };

    // prologue: G0 = {Q(128 rows x3), K0, V0}, G1 = {K1, V1}
#pragma unroll
    for (int m = 0; m < 3; m++) stage128(sm + AQ + m * AQT, Qp[m]);
#pragma unroll
    for (int m = 0; m < 3; m++) stage64(sm + AKB0 + m * ATILE, Kp[m]);
#pragma unroll
    for (int m = 0; m < 3; m++) stage64(sm + AVB0 + m * ATILE, Vp[m]);
    cpcommit();
#pragma unroll
    for (int m = 0; m < 3; m++) stage64(sm + AKB1 + m * ATILE, Kp[m] + 65536);
#pragma unroll
    for (int m = 0; m < 3; m++) stage64(sm + AVB1 + m * ATILE, Vp[m] + 65536);
    cpcommit();

    cpwait<1>();
    __syncthreads();               // Q, K0, V0 ready

    // persistent Q fragments: 3 streams x 4 k-steps x 4 regs = 48 regs
    u32 qf[3][4][4];
#pragma unroll
    for (int s3 = 0; s3 < 3; s3++) {
        const u32 qb = sm + AQ + s3 * AQT + (wid * 16 + lr) * AROW + lc * 16;
#pragma unroll
        for (int ks = 0; ks < 4; ks++)
            ldm4(qf[s3][ks], qb + ks * 32);
    }

    float co[3][4][2][4];          // [o][dg][nfd][frag]
    float coL[3][4];               // row-sum accumulators (ones-MMA)
#pragma unroll
    for (int o = 0; o < 3; o++) {
#pragma unroll
        for (int k = 0; k < 4; k++) coL[o][k] = 0.f;
#pragma unroll
        for (int dg = 0; dg < 4; dg++)
#pragma unroll
            for (int nf = 0; nf < 2; nf++)
#pragma unroll
                for (int k = 0; k < 4; k++) co[o][dg][nf][k] = 0.f;
    }

#pragma unroll 1
    for (int kt = 0; kt < 16; kt++) {
        const u32 kb0 = sm + ((kt & 1) ? AKB1 : AKB0);
        const u32 vb0 = sm + ((kt & 1) ? AVB1 : AVB0);

#pragma unroll
        for (int kg = 0; kg < 4; kg++) {
            // ---- scores for this 16-key group, 3 streams ----
            float sc[3][2][4];
#pragma unroll
            for (int s3 = 0; s3 < 3; s3++)
#pragma unroll
                for (int nf = 0; nf < 2; nf++)
#pragma unroll
                    for (int k = 0; k < 4; k++) sc[s3][nf][k] = 0.f;

#pragma unroll
            for (int s3 = 0; s3 < 3; s3++) {
                const u32 kb = kb0 + s3 * ATILE + (kg * 16 + lr) * AROW + lc * 16;
#pragma unroll
                for (int ks = 0; ks < 4; ks++) {
                    u32 kh[4];
                    ldm4(kh, kb + ks * 32);
                    mma_fp(sc[s3][0], qf[s3][ks], kh[0], kh[2]);
                    mma_fp(sc[s3][1], qf[s3][ks], kh[1], kh[3]);
                }
            }

            // ---- p = exp2(sa+sb) packed in-register as PV A-fragment ----
#pragma unroll
            for (int o = 0; o < 3; o++) {
                const int sa = (o == 0) ? 1 : 0;
                const int sb = (o == 2) ? 1 : 2;
                u32 pf[4];
                pf[0] = cvt_f16x2(ex2(sc[sa][0][0] + sc[sb][0][0]),
                                  ex2(sc[sa][0][1] + sc[sb][0][1]));
                pf[1] = cvt_f16x2(ex2(sc[sa][0][2] + sc[sb][0][2]),
                                  ex2(sc[sa][0][3] + sc[sb][0][3]));
                pf[2] = cvt_f16x2(ex2(sc[sa][1][0] + sc[sb][1][0]),
                                  ex2(sc[sa][1][1] + sc[sb][1][1]));
                pf[3] = cvt_f16x2(ex2(sc[sa][1][2] + sc[sb][1][2]),
                                  ex2(sc[sa][1][3] + sc[sb][1][3]));

                // row-sum via ones-vector MMA (fp32 accum on tensor pipe)
                mma_fp(coL[o], pf, ONESH2, ONESH2);

                // PV: O_o += P_frag @ V_o for this key group
                const u32 vbo = vb0 + o * ATILE + (kg * 16 + lr) * AROW + lc * 16;
#pragma unroll
                for (int dg = 0; dg < 4; dg++) {
                    u32 vh[4];
                    ldm4t(vh, vbo + dg * 32);
                    mma_fp(co[o][dg][0], pf, vh[0], vh[1]);
                    mma_fp(co[o][dg][1], pf, vh[2], vh[3]);
                }
            }
        }

        __syncthreads();           // all warps done reading buf[kt&1]
        if (kt + 2 < 16) {
            const u32 kbn = sm + ((kt & 1) ? AKB1 : AKB0);
            const u32 vbn = sm + ((kt & 1) ? AVB1 : AVB0);
            const size_t off = (size_t)(kt + 2) * 65536;
#pragma unroll
            for (int m = 0; m < 3; m++) stage64(kbn + m * ATILE, Kp[m] + off);
#pragma unroll
            for (int m = 0; m < 3; m++) stage64(vbn + m * ATILE, Vp[m] + off);
        }
        cpcommit();
        cpwait<1>();               // K/V(kt+1) complete
        __syncthreads();
    }

    // ---- epilogue: normalize by ones-MMA row sums, write AO fp16 ----
    const int r0 = wid * 16 + (lane >> 2);
#pragma unroll
    for (int o = 0; o < 3; o++) {
        f16* AH = g_AOh[o];
        const float iv0 = 1.0f / coL[o][0];
        const float iv1 = 1.0f / coL[o][2];
#pragma unroll
        for (int dg = 0; dg < 4; dg++)
#pragma unroll
            for (int nf = 0; nf < 2; nf++) {
                const int cl = dg * 16 + nf * 8 + 2 * (lane & 3);
                const size_t ga = ((size_t)((b << 10) + i0 + r0)) * 1024 + (h << 6) + cl;
                const size_t gb2 = ((size_t)((b << 10) + i0 + r0 + 8)) * 1024 + (h << 6) + cl;
                wstore2h(AH, ga,  co[o][dg][nf][0] * iv0, co[o][dg][nf][1] * iv0);
                wstore2h(AH, gb2, co[o][dg][nf][2] * iv1, co[o][dg][nf][3] * iv1);
            }
    }
}

// ============================================================
// split_all: x -> fp16, all 3 streams, one launch
// ============================================================
__global__ __launch_bounds__(256) void split_all(const float* __restrict__ x)
{
    const size_t gid = (size_t)blockIdx.x * 256 + threadIdx.x;
    const int s = (int)(gid >> 21);
    const size_t t = gid & 2097151ULL;
    const size_t idx = t * 4;
    const int m = (int)(idx >> 10), col = (int)(idx & 1023);
    const float4 v = *(const float4*)(x + ((size_t)m * 3 + s) * 1024 + col);
    f16* hi = &g_Ah[0][0] + s * NN + idx;
    ((u32*)hi)[0] = cvt_f16x2(v.x, v.y);
    ((u32*)hi)[1] = cvt_f16x2(v.z, v.w);
}

// ============================================================
// transposeAll: W^T (fp16) for all 4 weights
// ============================================================
__global__ __launch_bounds__(256) void transposeAll(
    const float* __restrict__ W0, const float* __restrict__ W1,
    const float* __restrict__ W2, const float* __restrict__ W3)
{
    __shared__ float t[32][33];
    const int w = blockIdx.z;
    const float* W = (w == 0) ? W0 : (w == 1) ? W1 : (w == 2) ? W2 : W3;
    f16* Th = &g_Wth[0][0] + (size_t)w * NW;
    int n0 = blockIdx.x << 5, k0 = blockIdx.y << 5;
    int tx = threadIdx.x, ty = threadIdx.y;
    for (int r = ty; r < 32; r += 8)
        t[r][tx] = W[(size_t)(k0 + r) * 1024 + n0 + tx];
    __syncthreads();
    for (int r = ty; r < 32; r += 8)
        Th[(size_t)(n0 + r) * 1024 + k0 + tx] = __float2half_rn(t[tx][r]);
}

// ============================================================
// Launch
// ============================================================
extern "C" void kernel_launch(void* const* d_in, const int* in_sizes, int n_in,
                              void* d_out, int out_size)
{
    const float* x  = (const float*)d_in[0];
    const float* Wq = (const float*)d_in[1];
    const float* bq = (const float*)d_in[2];
    const float* Wk = (const float*)d_in[3];
    const float* bk = (const float*)d_in[4];
    const float* Wv = (const float*)d_in[5];
    const float* bv = (const float*)d_in[6];
    const float* Wo = (const float*)d_in[7];
    const float* bo = (const float*)d_in[8];
    float* out = (float*)d_out;

    static bool attr_set = false;
    if (!attr_set) {
        cudaFuncSetAttribute(hproj, cudaFuncAttributeMaxDynamicSharedMemorySize, GEMM_SMEM);
        cudaFuncSetAttribute(hout, cudaFuncAttributeMaxDynamicSharedMemorySize, GEMM_SMEM);
        cudaFuncSetAttribute(hattn, cudaFuncAttributeMaxDynamicSharedMemorySize, ATTN_SMEM);
        attr_set = true;
    }

    f16 *Ah, *AOh;
    cudaGetSymbolAddress((void**)&Ah, g_Ah);
    cudaGetSymbolAddress((void**)&AOh, g_AOh);

    split_all<<<24576, 256>>>(x);
    transposeAll<<<dim3(32, 32, 4), dim3(32, 8)>>>(Wq, Wk, Wv, Wo);
    hproj<<<dim3(24, 64, 3), 256, GEMM_SMEM>>>(Ah, bq, bk, bv);
    hattn<<<dim3(8, 128), 256, ATTN_SMEM>>>();
    hout<<<dim3(8, 64, 3), 256, GEMM_SMEM>>>(AOh, bo, out);
}